// round 1
// baseline (speedup 1.0000x reference)
#include <cuda_runtime.h>
#include <math.h>

#define BB   128
#define CF   1024
#define RR   256
#define NATT 312
#define DV   300
#define NI   624      // stacked rows: [Q(312); P(312)]

// ---- scratch (device globals; no allocation in kernel_launch) ----
__device__ float g_vv[NATT * DV];            // normalized V
__device__ float g_QP[NI * CF];              // stacked Q,P  [624,1024]
__device__ float g_inorm[BB * RR];           // 1 / max(||img[b,:,r]||, eps)
__device__ float g_L[(size_t)BB * NI * RR];  // logits L1 (i<312) and L2 (i>=312)

// ---------------------------------------------------------------------------
// 1) vv = l2norm(V, axis=1)
// ---------------------------------------------------------------------------
__global__ void k_vnorm(const float* __restrict__ V) {
    int i = blockIdx.x;
    __shared__ float red[128];
    float s = 0.f;
    for (int k = threadIdx.x; k < DV; k += 128) {
        float v = V[i * DV + k];
        s += v * v;
    }
    red[threadIdx.x] = s;
    __syncthreads();
    for (int off = 64; off; off >>= 1) {
        if (threadIdx.x < off) red[threadIdx.x] += red[threadIdx.x + off];
        __syncthreads();
    }
    float inv = 1.f / fmaxf(sqrtf(red[0]), 1e-12f);
    for (int k = threadIdx.x; k < DV; k += 128)
        g_vv[i * DV + k] = V[i * DV + k] * inv;
}

// ---------------------------------------------------------------------------
// 2) QP[i,:] = vv[i] @ W1 (i<312)  /  vv[i-312] @ W2 (i>=312)
//    8 i-rows per block, 256 j-columns per block. 312 % 8 == 0 so every
//    block is entirely W1 or entirely W2.
// ---------------------------------------------------------------------------
__global__ void __launch_bounds__(256) k_qp(const float* __restrict__ W1,
                                            const float* __restrict__ W2) {
    int i0 = blockIdx.x * 8;
    const float* W = (i0 < NATT) ? W1 : W2;
    __shared__ float vrow[8][DV];
    for (int t = threadIdx.x; t < 8 * DV; t += 256) {
        int ii = t / DV, k = t % DV;
        int gi = i0 + ii;
        int iv = (gi < NATT) ? gi : gi - NATT;
        vrow[ii][k] = g_vv[iv * DV + k];
    }
    __syncthreads();
    int j = blockIdx.y * 256 + threadIdx.x;
    float acc[8] = {0, 0, 0, 0, 0, 0, 0, 0};
    for (int k = 0; k < DV; k++) {
        float w = W[k * CF + j];
#pragma unroll
        for (int ii = 0; ii < 8; ii++) acc[ii] += vrow[ii][k] * w;
    }
#pragma unroll
    for (int ii = 0; ii < 8; ii++) g_QP[(i0 + ii) * CF + j] = acc[ii];
}

// ---------------------------------------------------------------------------
// 3) g_inorm[b,r] = 1 / max(||img[b,:,r]||_2, eps)
// ---------------------------------------------------------------------------
__global__ void __launch_bounds__(256) k_nsq(const float* __restrict__ img) {
    int b = blockIdx.x;
    int r = threadIdx.x;
    const float* p = img + (size_t)b * CF * RR + r;
    float s = 0.f;
#pragma unroll 16
    for (int f = 0; f < CF; f++) {
        float v = p[(size_t)f * RR];
        s += v * v;
    }
    g_inorm[b * RR + r] = 1.f / fmaxf(sqrtf(s), 1e-12f);
}

// ---------------------------------------------------------------------------
// 4) Batched GEMM: L[b] = QP[624,1024] @ img[b][1024,256]
//    Tile 128(i) x 128(r) x 8(k), 256 threads, 8x8 per-thread, double-buffered.
//    grid = (2 r-tiles, 5 i-tiles (640, predicated to 624), 128 batches)
// ---------------------------------------------------------------------------
__global__ void __launch_bounds__(256) k_gemm(const float* __restrict__ img) {
    const int bx = blockIdx.x;            // r tile
    const int by = blockIdx.y;            // i tile
    const int b  = blockIdx.z;

    __shared__ float As[2][8][128];       // [buf][k][i]
    __shared__ float Bs[2][8][128];       // [buf][k][r]

    const float* A  = g_QP;
    const float* Bm = img + (size_t)b * CF * RR + bx * 128;  // B[k][r] = Bm[k*RR + r]

    const int tid  = threadIdx.x;
    const int arow = tid >> 1;            // 0..127 (i within tile)
    const int acol = (tid & 1) * 4;       // 0 or 4 (k within tile)
    const int brow = tid >> 5;            // 0..7   (k within tile)
    const int bcol = (tid & 31) * 4;      // 0..124 (r within tile)
    const int i0   = by * 128;

    const int ty = tid >> 4;              // 0..15
    const int tx = tid & 15;              // 0..15

    float acc[8][8];
#pragma unroll
    for (int u = 0; u < 8; u++)
#pragma unroll
        for (int v = 0; v < 8; v++) acc[u][v] = 0.f;

    float4 aReg, bReg;
    const int giA = i0 + arow;
    const bool aValid = (giA < NI);

    // prologue: load tile kt=0
    {
        aReg = aValid ? *(const float4*)&A[(size_t)giA * CF + acol]
                      : make_float4(0.f, 0.f, 0.f, 0.f);
        bReg = *(const float4*)&Bm[(size_t)brow * RR + bcol];
        As[0][acol + 0][arow] = aReg.x;
        As[0][acol + 1][arow] = aReg.y;
        As[0][acol + 2][arow] = aReg.z;
        As[0][acol + 3][arow] = aReg.w;
        *(float4*)&Bs[0][brow][bcol] = bReg;
    }
    __syncthreads();

    int buf = 0;
    for (int kt = 0; kt < CF / 8; kt++) {
        if (kt + 1 < CF / 8) {
            int kbase = (kt + 1) * 8;
            aReg = aValid ? *(const float4*)&A[(size_t)giA * CF + kbase + acol]
                          : make_float4(0.f, 0.f, 0.f, 0.f);
            bReg = *(const float4*)&Bm[(size_t)(kbase + brow) * RR + bcol];
        }
#pragma unroll
        for (int k = 0; k < 8; k++) {
            float4 a0 = *(const float4*)&As[buf][k][ty * 4];
            float4 a1 = *(const float4*)&As[buf][k][64 + ty * 4];
            float4 b0 = *(const float4*)&Bs[buf][k][tx * 4];
            float4 b1 = *(const float4*)&Bs[buf][k][64 + tx * 4];
            float av[8] = {a0.x, a0.y, a0.z, a0.w, a1.x, a1.y, a1.z, a1.w};
            float bv[8] = {b0.x, b0.y, b0.z, b0.w, b1.x, b1.y, b1.z, b1.w};
#pragma unroll
            for (int u = 0; u < 8; u++)
#pragma unroll
                for (int v = 0; v < 8; v++) acc[u][v] += av[u] * bv[v];
        }
        if (kt + 1 < CF / 8) {
            int nb = buf ^ 1;
            As[nb][acol + 0][arow] = aReg.x;
            As[nb][acol + 1][arow] = aReg.y;
            As[nb][acol + 2][arow] = aReg.z;
            As[nb][acol + 3][arow] = aReg.w;
            *(float4*)&Bs[nb][brow][bcol] = bReg;
            buf = nb;
            __syncthreads();
        }
    }

    // store C
#pragma unroll
    for (int u = 0; u < 8; u++) {
        int iRow = i0 + ((u < 4) ? (ty * 4 + u) : (64 + ty * 4 + u - 4));
        if (iRow >= NI) continue;
        float* dst = &g_L[((size_t)b * NI + iRow) * RR + bx * 128];
        float4 c0 = make_float4(acc[u][0], acc[u][1], acc[u][2], acc[u][3]);
        float4 c1 = make_float4(acc[u][4], acc[u][5], acc[u][6], acc[u][7]);
        *(float4*)&dst[tx * 4]      = c0;
        *(float4*)&dst[64 + tx * 4] = c1;
    }
}

// ---------------------------------------------------------------------------
// 5) Pred[b,i] = sum_r softmax_r(L1[b,i,r]*inorm[b,r]) * (L2[b,i,r]*inorm[b,r])
//    one warp per (b,i)
// ---------------------------------------------------------------------------
__global__ void __launch_bounds__(256) k_out(float* __restrict__ out) {
    int gwarp = (blockIdx.x * blockDim.x + threadIdx.x) >> 5;
    int lane  = threadIdx.x & 31;
    if (gwarp >= BB * NATT) return;
    int b = gwarp / NATT;
    int i = gwarp - b * NATT;

    const float* L1  = &g_L[((size_t)b * NI + i) * RR];
    const float* L2  = &g_L[((size_t)b * NI + i + NATT) * RR];
    const float* inn = &g_inorm[b * RR];

    float l1[8], l2[8];
    float m = -INFINITY;
#pragma unroll
    for (int u = 0; u < 8; u++) {
        int r = lane + u * 32;
        float s = inn[r];
        l1[u] = L1[r] * s;
        l2[u] = L2[r] * s;
        m = fmaxf(m, l1[u]);
    }
#pragma unroll
    for (int off = 16; off; off >>= 1)
        m = fmaxf(m, __shfl_xor_sync(0xffffffffu, m, off));

    float se = 0.f, sd = 0.f;
#pragma unroll
    for (int u = 0; u < 8; u++) {
        float e = expf(l1[u] - m);
        se += e;
        sd += e * l2[u];
    }
#pragma unroll
    for (int off = 16; off; off >>= 1) {
        se += __shfl_xor_sync(0xffffffffu, se, off);
        sd += __shfl_xor_sync(0xffffffffu, sd, off);
    }
    if (lane == 0) out[b * NATT + i] = sd / se;
}

// ---------------------------------------------------------------------------
extern "C" void kernel_launch(void* const* d_in, const int* in_sizes, int n_in,
                              void* d_out, int out_size) {
    const float* img = (const float*)d_in[0];  // [128,1024,16,16]
    const float* V   = (const float*)d_in[1];  // [312,300]
    const float* W1  = (const float*)d_in[2];  // [300,1024]
    const float* W2  = (const float*)d_in[3];  // [300,1024]
    float* out = (float*)d_out;                // [128,312]

    k_vnorm<<<NATT, 128>>>(V);
    k_qp<<<dim3(NI / 8, CF / 256), 256>>>(W1, W2);
    k_nsq<<<BB, RR>>>(img);
    k_gemm<<<dim3(2, 5, BB), 256>>>(img);
    int warps = BB * NATT;
    k_out<<<(warps + 7) / 8, 256>>>(out);
}

// round 3
// speedup vs baseline: 1.9621x; 1.9621x over previous
#include <cuda_runtime.h>
#include <cuda_bf16.h>
#include <math.h>
#include <stdint.h>

#define BB   128
#define CF   1024
#define RR   256
#define NATT 312
#define DV   300
#define NI   624
#define NIP  640

// ---------------- scratch (device globals) ----------------
__device__ float         g_vv[NATT * DV];
__device__ __nv_bfloat16 g_Ah[NIP * CF];              // interleaved [2i]=Q_i,[2i+1]=P_i
__device__ __nv_bfloat16 g_Al[NIP * CF];
__device__ __nv_bfloat16 g_Bh[(size_t)BB * RR * CF];  // [b][r][k] normalized, hi
__device__ __nv_bfloat16 g_Bl[(size_t)BB * RR * CF];  // lo
__device__ float         g_inorm[BB * RR];

// ---------------- helpers ----------------
__device__ __forceinline__ uint32_t smem_u32(const void* p) {
    uint32_t a;
    asm("{ .reg .u64 t; cvta.to.shared.u64 t, %1; cvt.u32.u64 %0, t; }" : "=r"(a) : "l"(p));
    return a;
}
#define CP_ASYNC16(dst, src) \
    asm volatile("cp.async.cg.shared.global [%0], [%1], 16;" :: "r"(dst), "l"(src) : "memory")
#define CP_COMMIT() asm volatile("cp.async.commit_group;" ::: "memory")
#define CP_WAIT(N)  asm volatile("cp.async.wait_group %0;" :: "n"(N) : "memory")

__device__ __forceinline__ void ldsm4(uint32_t* r, uint32_t addr) {
    asm volatile("ldmatrix.sync.aligned.m8n8.x4.shared.b16 {%0,%1,%2,%3}, [%4];"
                 : "=r"(r[0]), "=r"(r[1]), "=r"(r[2]), "=r"(r[3]) : "r"(addr));
}
__device__ __forceinline__ void ldsm2(uint32_t* r, uint32_t addr) {
    asm volatile("ldmatrix.sync.aligned.m8n8.x2.shared.b16 {%0,%1}, [%2];"
                 : "=r"(r[0]), "=r"(r[1]) : "r"(addr));
}
__device__ __forceinline__ void mma_bf16(float* c, const uint32_t* a, const uint32_t* b) {
    asm volatile(
        "mma.sync.aligned.m16n8k16.row.col.f32.bf16.bf16.f32 "
        "{%0,%1,%2,%3}, {%4,%5,%6,%7}, {%8,%9}, {%0,%1,%2,%3};"
        : "+f"(c[0]), "+f"(c[1]), "+f"(c[2]), "+f"(c[3])
        : "r"(a[0]), "r"(a[1]), "r"(a[2]), "r"(a[3]), "r"(b[0]), "r"(b[1]));
}

// ---------------------------------------------------------------------------
// 1) vv = l2norm(V, axis=1)
// ---------------------------------------------------------------------------
__global__ void k_vnorm(const float* __restrict__ V) {
    int i = blockIdx.x;
    __shared__ float red[128];
    float s = 0.f;
    for (int k = threadIdx.x; k < DV; k += 128) { float v = V[i * DV + k]; s += v * v; }
    red[threadIdx.x] = s; __syncthreads();
    for (int off = 64; off; off >>= 1) {
        if (threadIdx.x < off) red[threadIdx.x] += red[threadIdx.x + off];
        __syncthreads();
    }
    float inv = 1.f / fmaxf(sqrtf(red[0]), 1e-12f);
    for (int k = threadIdx.x; k < DV; k += 128) g_vv[i * DV + k] = V[i * DV + k] * inv;
}

// ---------------------------------------------------------------------------
// 2) QP rows, interleaved, hi/lo bf16 split. grid (39, 4, 2)
// ---------------------------------------------------------------------------
__global__ void __launch_bounds__(256) k_qp(const float* __restrict__ W1,
                                            const float* __restrict__ W2) {
    int i0 = blockIdx.x * 8;
    int z  = blockIdx.z;
    const float* W = z ? W2 : W1;
    __shared__ float vrow[8][DV];
    for (int t = threadIdx.x; t < 8 * DV; t += 256) {
        int ii = t / DV, k = t % DV;
        vrow[ii][k] = g_vv[(i0 + ii) * DV + k];
    }
    __syncthreads();
    int j = blockIdx.y * 256 + threadIdx.x;
    float acc[8] = {0,0,0,0,0,0,0,0};
    for (int k = 0; k < DV; k++) {
        float w = W[k * CF + j];
#pragma unroll
        for (int ii = 0; ii < 8; ii++) acc[ii] += vrow[ii][k] * w;
    }
#pragma unroll
    for (int ii = 0; ii < 8; ii++) {
        int row = 2 * (i0 + ii) + z;
        float x = acc[ii];
        __nv_bfloat16 h = __float2bfloat16(x);
        __nv_bfloat16 l = __float2bfloat16(x - __bfloat162float(h));
        g_Ah[row * CF + j] = h;
        g_Al[row * CF + j] = l;
    }
}

__global__ void k_padA() {
    int t = blockIdx.x * 256 + threadIdx.x;
    if (t < (NIP - NI) * CF) {
        g_Ah[NI * CF + t] = __float2bfloat16(0.f);
        g_Al[NI * CF + t] = __float2bfloat16(0.f);
    }
}

// ---------------------------------------------------------------------------
// 3) inverse column norms
// ---------------------------------------------------------------------------
__global__ void __launch_bounds__(1024) k_nsq(const float* __restrict__ img) {
    int b = blockIdx.x;
    int r = threadIdx.x & 255;
    int q = threadIdx.x >> 8;
    const float* p = img + (size_t)b * CF * RR + r;
    float s = 0.f;
#pragma unroll 8
    for (int f = q * 256; f < q * 256 + 256; f++) { float v = p[(size_t)f * RR]; s += v * v; }
    __shared__ float red[1024];
    red[threadIdx.x] = s; __syncthreads();
    if (q == 0) {
        s = red[r] + red[r + 256] + red[r + 512] + red[r + 768];
        g_inorm[b * RR + r] = 1.f / fmaxf(sqrtf(s), 1e-12f);
    }
}

// ---------------------------------------------------------------------------
// 4) transpose + normalize + hi/lo convert
// ---------------------------------------------------------------------------
__global__ void __launch_bounds__(256) k_bt(const float* __restrict__ img) {
    int b  = blockIdx.z;
    int k0 = blockIdx.y * 32;
    int r0 = blockIdx.x * 32;
    __shared__ float t[32][33];
    const float* src = img + (size_t)b * CF * RR;
#pragma unroll
    for (int d = 0; d < 4; d++) {
        int ky = threadIdx.y + 8 * d;
        t[ky][threadIdx.x] = src[(size_t)(k0 + ky) * RR + r0 + threadIdx.x];
    }
    __syncthreads();
#pragma unroll
    for (int d = 0; d < 4; d++) {
        int ry = threadIdx.y + 8 * d;
        int r = r0 + ry;
        float s = g_inorm[b * RR + r];
        float v = t[threadIdx.x][ry] * s;
        __nv_bfloat16 h = __float2bfloat16(v);
        __nv_bfloat16 l = __float2bfloat16(v - __bfloat162float(h));
        size_t o = ((size_t)b * RR + r) * CF + k0 + threadIdx.x;
        g_Bh[o] = h;
        g_Bl[o] = l;
    }
}

// ---------------------------------------------------------------------------
// 5) warp-MMA GEMM (3-term bf16) + fused softmax-dot epilogue.
//    CTA: M=64, N=256, K chunks of 32, double-buffered cp.async.
//    grid (10 itiles, 128 b), 256 threads, 2 CTA/SM.
// ---------------------------------------------------------------------------
#define KC     32
#define NCH    (CF / KC)      // 32
#define SROW   80             // KC*2 + 16B pad (conflict-free ldmatrix)
#define A_H    0
#define A_L    5120           // 64*80
#define B_H    10240
#define B_L    30720          // +256*80
#define STG    51200
#define SMEM_DYN (2 * STG)    // 102400
#define CSTRIDE 264

__global__ void __launch_bounds__(256, 2) k_gemm_mma(float* __restrict__ out) {
    extern __shared__ __align__(128) char dsm[];
    const int tid   = threadIdx.x;
    const int wid   = tid >> 5;
    const int lane  = tid & 31;
    const int itile = blockIdx.x;
    const int b     = blockIdx.y;
    const int mw    = wid >> 2;           // 0..1
    const int nw    = wid & 3;            // 0..3

    const uint32_t sbase = smem_u32(dsm);

    const char* pAh = (const char*)g_Ah + (size_t)(itile * 64) * CF * 2;
    const char* pAl = (const char*)g_Al + (size_t)(itile * 64) * CF * 2;
    const char* pBh = (const char*)g_Bh + (size_t)b * RR * CF * 2;
    const char* pBl = (const char*)g_Bl + (size_t)b * RR * CF * 2;

    // cp.async source/dest lane mapping
    const int arow = tid >> 2, aj = tid & 3;

    // ldmatrix lane offsets
    const uint32_t aoff = (uint32_t)((mw * 32 + (lane & 15)) * SROW + ((lane >> 4) << 4));
    const uint32_t boff = (uint32_t)((nw * 64 + (lane & 7)) * SROW + ((lane & 8) << 1));

    float acc[2][8][4];
#pragma unroll
    for (int mi = 0; mi < 2; mi++)
#pragma unroll
        for (int ni = 0; ni < 8; ni++)
#pragma unroll
            for (int u = 0; u < 4; u++) acc[mi][ni][u] = 0.f;

    // ---- chunk loader ----
    auto load_chunk = [&](int buf, int c) {
        const size_t kb = (size_t)c * (KC * 2);
        const uint32_t st = sbase + buf * STG;
        // A: 64 rows x 64B, hi+lo (1 xfer each per thread)
        CP_ASYNC16(st + A_H + arow * SROW + aj * 16,
                   pAh + (size_t)arow * (CF * 2) + kb + aj * 16);
        CP_ASYNC16(st + A_L + arow * SROW + aj * 16,
                   pAl + (size_t)arow * (CF * 2) + kb + aj * 16);
        // B: 256 rows x 64B, hi+lo (4 xfers each per thread)
#pragma unroll
        for (int it = 0; it < 4; it++) {
            int row = arow + it * 64;
            CP_ASYNC16(st + B_H + row * SROW + aj * 16,
                       pBh + (size_t)row * (CF * 2) + kb + aj * 16);
            CP_ASYNC16(st + B_L + row * SROW + aj * 16,
                       pBl + (size_t)row * (CF * 2) + kb + aj * 16);
        }
    };

    load_chunk(0, 0);
    CP_COMMIT();

    for (int c = 0; c < NCH; c++) {
        const int buf = c & 1;
        if (c + 1 < NCH) { load_chunk(buf ^ 1, c + 1); CP_COMMIT(); CP_WAIT(1); }
        else             { CP_WAIT(0); }
        __syncthreads();

        const uint32_t st = sbase + buf * STG;
#pragma unroll
        for (int ks = 0; ks < 2; ks++) {
            const uint32_t kb = ks * 32;   // 16 bf16 = 32 bytes
            uint32_t ah[2][4], al[2][4];
#pragma unroll
            for (int mi = 0; mi < 2; mi++) {
                ldsm4(ah[mi], st + A_H + aoff + mi * (16 * SROW) + kb);
                ldsm4(al[mi], st + A_L + aoff + mi * (16 * SROW) + kb);
            }
#pragma unroll
            for (int ni = 0; ni < 8; ni++) {
                uint32_t bh[2], bl[2];
                ldsm2(bh, st + B_H + boff + ni * (8 * SROW) + kb);
                ldsm2(bl, st + B_L + boff + ni * (8 * SROW) + kb);
#pragma unroll
                for (int mi = 0; mi < 2; mi++) {
                    mma_bf16(acc[mi][ni], ah[mi], bh);
                    mma_bf16(acc[mi][ni], ah[mi], bl);
                    mma_bf16(acc[mi][ni], al[mi], bh);
                }
            }
        }
        __syncthreads();
    }

    // ---- epilogue: accums -> smem C[64][264] ----
    float* Cs = (float*)dsm;
    const int m0 = mw * 32, n0 = nw * 64;
#pragma unroll
    for (int mi = 0; mi < 2; mi++)
#pragma unroll
        for (int ni = 0; ni < 8; ni++) {
            int r0 = m0 + mi * 16 + (lane >> 2);
            int c0 = n0 + ni * 8 + 2 * (lane & 3);
            Cs[r0 * CSTRIDE + c0]           = acc[mi][ni][0];
            Cs[r0 * CSTRIDE + c0 + 1]       = acc[mi][ni][1];
            Cs[(r0 + 8) * CSTRIDE + c0]     = acc[mi][ni][2];
            Cs[(r0 + 8) * CSTRIDE + c0 + 1] = acc[mi][ni][3];
        }
    __syncthreads();

    // ---- softmax-dot: 32 row-pairs, 4 per warp ----
#pragma unroll
    for (int pp = 0; pp < 4; pp++) {
        int p = wid * 4 + pp;                  // 0..31
        const float* r1 = Cs + (2 * p) * CSTRIDE;
        const float* r2 = Cs + (2 * p + 1) * CSTRIDE;
        float l1[8], l2[8];
        float m = -INFINITY;
#pragma unroll
        for (int u = 0; u < 8; u++) {
            int r = lane + u * 32;
            l1[u] = r1[r];
            l2[u] = r2[r];
            m = fmaxf(m, l1[u]);
        }
#pragma unroll
        for (int off = 16; off; off >>= 1)
            m = fmaxf(m, __shfl_xor_sync(0xffffffffu, m, off));
        float se = 0.f, sd = 0.f;
#pragma unroll
        for (int u = 0; u < 8; u++) {
            float e = __expf(l1[u] - m);
            se += e;
            sd += e * l2[u];
        }
#pragma unroll
        for (int off = 16; off; off >>= 1) {
            se += __shfl_xor_sync(0xffffffffu, se, off);
            sd += __shfl_xor_sync(0xffffffffu, sd, off);
        }
        int i = itile * 32 + p;
        if (lane == 0 && i < NATT) out[b * NATT + i] = sd / se;
    }
}

// ---------------------------------------------------------------------------
extern "C" void kernel_launch(void* const* d_in, const int* in_sizes, int n_in,
                              void* d_out, int out_size) {
    const float* img = (const float*)d_in[0];
    const float* V   = (const float*)d_in[1];
    const float* W1  = (const float*)d_in[2];
    const float* W2  = (const float*)d_in[3];
    float* out = (float*)d_out;

    cudaFuncSetAttribute(k_gemm_mma, cudaFuncAttributeMaxDynamicSharedMemorySize, SMEM_DYN);

    k_vnorm<<<NATT, 128>>>(V);
    k_qp<<<dim3(NATT / 8, CF / 256, 2), 256>>>(W1, W2);
    k_padA<<<((NIP - NI) * CF + 255) / 256, 256>>>();
    k_nsq<<<BB, 1024>>>(img);
    k_bt<<<dim3(RR / 32, CF / 32, BB), dim3(32, 8)>>>(img);
    k_gemm_mma<<<dim3(10, BB), 256, SMEM_DYN>>>(out);
}